// round 2
// baseline (speedup 1.0000x reference)
#include <cuda_runtime.h>
#include <cstdint>

// Problem constants
#define BB 8
#define TT 128
#define S_ENC 400
#define HH 256
#define VV 50257

#define TABLE 2048
#define TMASK (TABLE - 1)
#define THREADS 256
#define NWARPS (THREADS / 32)

__device__ __forceinline__ unsigned hash_tok(unsigned t) {
    return (t * 2654435761u) & TMASK;
}

__global__ void __launch_bounds__(THREADS, 8)
pointer_gen_fused(const int*   __restrict__ tokens,   // [B, S]
                  const float* __restrict__ ctx,      // [B, T, H]
                  const float* __restrict__ dec_in,   // [B, T, H]
                  const float* __restrict__ dec_out,  // [B, T, H]
                  const float* __restrict__ vocab,    // [B, T, V]
                  const float* __restrict__ attn,     // [B, T, S]
                  const float* __restrict__ Wc, const float* __restrict__ bc,
                  const float* __restrict__ Wo, const float* __restrict__ bo,
                  const float* __restrict__ Wi, const float* __restrict__ bi,
                  float*       __restrict__ out)      // [B, T, V]
{
    __shared__ int   keys[TABLE];
    __shared__ float vals[TABLE];
    __shared__ float red[NWARPS];
    __shared__ float s_pg, s_lse;
    __shared__ int   s_nd;

    const int row  = blockIdx.x;          // b*T + t
    const int b    = row / TT;
    const int tid  = threadIdx.x;
    const int lane = tid & 31;
    const int warp = tid >> 5;

    // ---- init shared table ----
    #pragma unroll
    for (int i = tid; i < TABLE; i += THREADS) { keys[i] = -1; vals[i] = 0.f; }
    if (tid == 0) s_nd = 0;

    // ---- p_gen partial dot (H == THREADS) ----
    const float* cr  = ctx     + (size_t)row * HH;
    const float* dir = dec_in  + (size_t)row * HH;
    const float* dor = dec_out + (size_t)row * HH;
    float p = cr[tid] * Wc[tid] + dor[tid] * Wo[tid] + dir[tid] * Wi[tid];
    #pragma unroll
    for (int o = 16; o; o >>= 1) p += __shfl_down_sync(0xffffffffu, p, o);

    __syncthreads();                      // shared init complete
    if (lane == 0) red[warp] = p;
    __syncthreads();
    if (tid == 0) {
        float s = bc[0] + bo[0] + bi[0];
        #pragma unroll
        for (int w = 0; w < NWARPS; w++) s += red[w];
        s_pg = 1.f / (1.f + expf(-s));
    }

    // ---- scatter attn into hash table (dedup + accumulate) ----
    const int*   tokb = tokens + b * S_ENC;
    const float* ar   = attn + (size_t)row * S_ENC;
    for (int s = tid; s < S_ENC; s += THREADS) {
        int   tok = tokb[s];
        float a   = ar[s];
        unsigned slot = hash_tok((unsigned)tok);
        while (true) {
            int prev = atomicCAS(&keys[slot], -1, tok);
            if (prev == -1 || prev == tok) {
                atomicAdd(&vals[slot], a);
                if (prev == -1) atomicAdd(&s_nd, 1);
                break;
            }
            slot = (slot + 1) & TMASK;
        }
    }
    __syncthreads();

    // ---- max over table values (implicit zeros -> m >= 0) ----
    float m = 0.f;
    for (int i = tid; i < TABLE; i += THREADS)
        if (keys[i] != -1) m = fmaxf(m, vals[i]);
    #pragma unroll
    for (int o = 16; o; o >>= 1) m = fmaxf(m, __shfl_down_sync(0xffffffffu, m, o));
    if (lane == 0) red[warp] = m;
    __syncthreads();
    float mblk = red[0];
    #pragma unroll
    for (int w = 1; w < NWARPS; w++) mblk = fmaxf(mblk, red[w]);
    __syncthreads();                      // red reuse below

    // ---- sum of exp over table + implicit zeros ----
    float se = 0.f;
    for (int i = tid; i < TABLE; i += THREADS)
        if (keys[i] != -1) se += expf(vals[i] - mblk);
    #pragma unroll
    for (int o = 16; o; o >>= 1) se += __shfl_down_sync(0xffffffffu, se, o);
    if (lane == 0) red[warp] = se;
    __syncthreads();
    if (tid == 0) {
        float s = 0.f;
        #pragma unroll
        for (int w = 0; w < NWARPS; w++) s += red[w];
        s += (float)(VV - s_nd) * expf(-mblk);
        s_lse = mblk + logf(s);
    }
    __syncthreads();

    const float pg    = s_pg;
    const float one_m = 1.f - pg;
    const float base  = -one_m * s_lse;   // pure-stream value: vocab*pg + base

    const float* vr   = vocab + (size_t)row * VV;
    float*       orow = out   + (size_t)row * VV;

    // ================= Phase B: PURE stream (no copy handling) =================
    // alignment peel (V odd -> row base alternates 16B alignment)
    int head = (int)((4 - (((size_t)row * VV) & 3)) & 3);
    for (int v = tid; v < head; v += THREADS)
        orow[v] = vr[v] * pg + base;

    const int n4 = (VV - head) >> 2;
    const float4* vr4 = (const float4*)(vr + head);
    float4*       or4 = (float4*)(orow + head);

    // unrolled-by-4 main loop: 4 independent LDG.128 in flight per thread
    const int chunk = THREADS * 4;
    int i = tid;
    int nmain = n4 - (n4 % chunk);        // count covered by full chunks? (see below)
    // simpler: blocked loop with bound check per sub-load batched
    for (int ibase = 0; ibase + chunk <= n4; ibase += chunk) {
        int i0 = ibase + tid;
        float4 a = vr4[i0];
        float4 bq = vr4[i0 + THREADS];
        float4 c = vr4[i0 + 2 * THREADS];
        float4 d = vr4[i0 + 3 * THREADS];
        float4 ya, yb, yc, yd;
        ya.x = a.x * pg + base; ya.y = a.y * pg + base; ya.z = a.z * pg + base; ya.w = a.w * pg + base;
        yb.x = bq.x * pg + base; yb.y = bq.y * pg + base; yb.z = bq.z * pg + base; yb.w = bq.w * pg + base;
        yc.x = c.x * pg + base; yc.y = c.y * pg + base; yc.z = c.z * pg + base; yc.w = c.w * pg + base;
        yd.x = d.x * pg + base; yd.y = d.y * pg + base; yd.z = d.z * pg + base; yd.w = d.w * pg + base;
        or4[i0] = ya;
        or4[i0 + THREADS] = yb;
        or4[i0 + 2 * THREADS] = yc;
        or4[i0 + 3 * THREADS] = yd;
        i = ibase + chunk;
    }
    // tail quads
    for (int j = (n4 / chunk) * chunk + tid; j < n4; j += THREADS) {
        float4 a = vr4[j];
        float4 y;
        y.x = a.x * pg + base; y.y = a.y * pg + base; y.z = a.z * pg + base; y.w = a.w * pg + base;
        or4[j] = y;
    }
    // scalar tail
    for (int v = head + n4 * 4 + tid; v < VV; v += THREADS)
        orow[v] = vr[v] * pg + base;

    // ================= Phase C: sparse fixup (adds copy term) =================
    // Block-scope visibility of this block's own global writes after syncthreads.
    __syncthreads();
    for (int t = tid; t < TABLE; t += THREADS) {
        int k = keys[t];
        if (k != -1) {
            // lines just written by this block -> L1/L2 hot
            orow[k] += one_m * vals[t];
        }
    }
}

extern "C" void kernel_launch(void* const* d_in, const int* in_sizes, int n_in,
                              void* d_out, int out_size)
{
    // metadata order (setup_inputs dict order):
    // 0 input_tokens [B,S] int32
    // 1 context [B,T,H]  2 decoder_input  3 decoder_output
    // 4 vocab_dist [B,T,V]  5 attn_dist [B,T,S]  6 encoder_outputs (unused)
    // 7 Wc  8 bc  9 Wo  10 bo  11 Wi  12 bi
    const int*   tokens  = (const int*)  d_in[0];
    const float* ctx     = (const float*)d_in[1];
    const float* dec_in  = (const float*)d_in[2];
    const float* dec_out = (const float*)d_in[3];
    const float* vocab   = (const float*)d_in[4];
    const float* attn    = (const float*)d_in[5];
    const float* Wc      = (const float*)d_in[7];
    const float* bc      = (const float*)d_in[8];
    const float* Wo      = (const float*)d_in[9];
    const float* bo      = (const float*)d_in[10];
    const float* Wi      = (const float*)d_in[11];
    const float* bi      = (const float*)d_in[12];
    float* out = (float*)d_out;

    pointer_gen_fused<<<BB * TT, THREADS>>>(tokens, ctx, dec_in, dec_out, vocab,
                                            attn, Wc, bc, Wo, bo, Wi, bi, out);
}

// round 3
// speedup vs baseline: 1.0467x; 1.0467x over previous
#include <cuda_runtime.h>
#include <cstdint>

// Problem constants
#define BB 8
#define TT 128
#define S_ENC 400
#define HH 256
#define VV 50257

#define TABLE 1024
#define TMASK (TABLE - 1)
#define NWORDS ((VV + 31) / 32)   // 1571 bitmap words
#define THREADS 256
#define NWARPS (THREADS / 32)

__device__ __forceinline__ unsigned hash_tok(unsigned t) {
    return (t * 2654435761u) & TMASK;
}

__global__ void __launch_bounds__(THREADS, 4)
pointer_gen_fused(const int*   __restrict__ tokens,   // [B, S]
                  const float* __restrict__ ctx,      // [B, T, H]
                  const float* __restrict__ dec_in,   // [B, T, H]
                  const float* __restrict__ dec_out,  // [B, T, H]
                  const float* __restrict__ vocab,    // [B, T, V]
                  const float* __restrict__ attn,     // [B, T, S]
                  const float* __restrict__ Wc, const float* __restrict__ bc,
                  const float* __restrict__ Wo, const float* __restrict__ bo,
                  const float* __restrict__ Wi, const float* __restrict__ bi,
                  float*       __restrict__ out)      // [B, T, V]
{
    __shared__ int      keys[TABLE];
    __shared__ float    vals[TABLE];
    __shared__ unsigned bitmap[NWORDS + 1];   // +1 pad word for funnel shift
    __shared__ float    red[NWARPS];
    __shared__ float    s_pg, s_lse;
    __shared__ int      s_nd;

    const int row  = blockIdx.x;          // b*T + t
    const int b    = row / TT;
    const int tid  = threadIdx.x;
    const int lane = tid & 31;
    const int warp = tid >> 5;

    // ---- init shared ----
    #pragma unroll
    for (int i = tid; i < TABLE; i += THREADS) { keys[i] = -1; vals[i] = 0.f; }
    for (int i = tid; i < NWORDS + 1; i += THREADS) bitmap[i] = 0u;
    if (tid == 0) s_nd = 0;

    // ---- p_gen partial dot (H == THREADS) ----
    const float* cr  = ctx     + (size_t)row * HH;
    const float* dir = dec_in  + (size_t)row * HH;
    const float* dor = dec_out + (size_t)row * HH;
    float p = cr[tid] * Wc[tid] + dor[tid] * Wo[tid] + dir[tid] * Wi[tid];
    #pragma unroll
    for (int o = 16; o; o >>= 1) p += __shfl_down_sync(0xffffffffu, p, o);

    __syncthreads();                      // shared init complete
    if (lane == 0) red[warp] = p;
    __syncthreads();
    if (tid == 0) {
        float s = bc[0] + bo[0] + bi[0];
        #pragma unroll
        for (int w = 0; w < NWARPS; w++) s += red[w];
        s_pg = 1.f / (1.f + expf(-s));
    }

    // ---- scatter attn into hash table (dedup + accumulate) ----
    const int*   tokb = tokens + b * S_ENC;
    const float* ar   = attn + (size_t)row * S_ENC;
    for (int s = tid; s < S_ENC; s += THREADS) {
        int   tok = tokb[s];
        float a   = ar[s];
        unsigned slot = hash_tok((unsigned)tok);
        while (true) {
            int prev = atomicCAS(&keys[slot], -1, tok);
            if (prev == -1 || prev == tok) {
                atomicAdd(&vals[slot], a);
                if (prev == -1) {
                    atomicAdd(&s_nd, 1);
                    atomicOr(&bitmap[tok >> 5], 1u << (tok & 31));
                }
                break;
            }
            slot = (slot + 1) & TMASK;
        }
    }
    __syncthreads();

    // ---- lse in ONE pass: vals <= ~10, exp cannot overflow, skip max pass ----
    // lse = log( (V - nd)*exp(0) + sum_occupied exp(val) )
    float se = 0.f;
    #pragma unroll
    for (int i = tid; i < TABLE; i += THREADS)
        if (keys[i] != -1) se += expf(vals[i]);
    #pragma unroll
    for (int o = 16; o; o >>= 1) se += __shfl_down_sync(0xffffffffu, se, o);
    if (lane == 0) red[warp] = se;
    __syncthreads();
    if (tid == 0) {
        float s = 0.f;
        #pragma unroll
        for (int w = 0; w < NWARPS; w++) s += red[w];
        s_lse = logf(s + (float)(VV - s_nd));
    }
    __syncthreads();

    const float pg    = s_pg;
    const float one_m = 1.f - pg;
    const float base  = -one_m * s_lse;   // out = vocab*pg + one_m*copy + base

    const float* vr   = vocab + (size_t)row * VV;
    float*       orow = out   + (size_t)row * VV;

    // ---- streaming pass: peel to 16B pointer alignment ----
    int head = (int)((4 - (((size_t)row * VV) & 3)) & 3);
    for (int v = tid; v < head; v += THREADS) {
        float c = 0.f;
        if ((bitmap[v >> 5] >> (v & 31)) & 1u) {
            unsigned slot = hash_tok((unsigned)v);
            while (keys[slot] != v) slot = (slot + 1) & TMASK;
            c = vals[slot];
        }
        orow[v] = vr[v] * pg + one_m * c + base;
    }

    const int n4 = (VV - head) >> 2;
    const float4* vr4 = (const float4*)(vr + head);
    float4*       or4 = (float4*)(orow + head);

    #pragma unroll 2
    for (int i = tid; i < n4; i += THREADS) {
        float4 x = __ldcs(&vr4[i]);
        float4 y;
        y.x = x.x * pg + base;
        y.y = x.y * pg + base;
        y.z = x.z * pg + base;
        y.w = x.w * pg + base;

        // single funnel-shift bitmap test covering the whole quad
        int vb = head + i * 4;
        unsigned w0 = bitmap[vb >> 5];
        unsigned w1 = bitmap[(vb >> 5) + 1];
        unsigned bits = __funnelshift_r(w0, w1, vb & 31) & 0xFu;
        if (bits) {   // rare (~3% of quads)
            #pragma unroll
            for (int k = 0; k < 4; k++) {
                if (bits & (1u << k)) {
                    int v = vb + k;
                    unsigned slot = hash_tok((unsigned)v);
                    while (keys[slot] != v) slot = (slot + 1) & TMASK;
                    float c = one_m * vals[slot];
                    if (k == 0) y.x += c;
                    else if (k == 1) y.y += c;
                    else if (k == 2) y.z += c;
                    else y.w += c;
                }
            }
        }
        __stcs(&or4[i], y);
    }

    for (int v = head + n4 * 4 + tid; v < VV; v += THREADS) {
        float c = 0.f;
        if ((bitmap[v >> 5] >> (v & 31)) & 1u) {
            unsigned slot = hash_tok((unsigned)v);
            while (keys[slot] != v) slot = (slot + 1) & TMASK;
            c = vals[slot];
        }
        orow[v] = vr[v] * pg + one_m * c + base;
    }
}

extern "C" void kernel_launch(void* const* d_in, const int* in_sizes, int n_in,
                              void* d_out, int out_size)
{
    // metadata order (setup_inputs dict order):
    // 0 input_tokens [B,S] int32
    // 1 context [B,T,H]  2 decoder_input  3 decoder_output
    // 4 vocab_dist [B,T,V]  5 attn_dist [B,T,S]  6 encoder_outputs (unused)
    // 7 Wc  8 bc  9 Wo  10 bo  11 Wi  12 bi
    const int*   tokens  = (const int*)  d_in[0];
    const float* ctx     = (const float*)d_in[1];
    const float* dec_in  = (const float*)d_in[2];
    const float* dec_out = (const float*)d_in[3];
    const float* vocab   = (const float*)d_in[4];
    const float* attn    = (const float*)d_in[5];
    const float* Wc      = (const float*)d_in[7];
    const float* bc      = (const float*)d_in[8];
    const float* Wo      = (const float*)d_in[9];
    const float* bo      = (const float*)d_in[10];
    const float* Wi      = (const float*)d_in[11];
    const float* bi      = (const float*)d_in[12];
    float* out = (float*)d_out;

    pointer_gen_fused<<<BB * TT, THREADS>>>(tokens, ctx, dec_in, dec_out, vocab,
                                            attn, Wc, bc, Wo, bo, Wi, bi, out);
}